// round 4
// baseline (speedup 1.0000x reference)
#include <cuda_runtime.h>
#include <cuda_bf16.h>

#define N_NODES 50000
#define N_EDGES 800000
#define D 64
#define CAP 128   // bucket capacity; P(deg>=128 | Poisson(16)) < 1e-60

// Scratch (device globals — no allocation allowed in kernel_launch)
__device__ __align__(16) float g_M[(size_t)N_NODES * D];  // relu(h @ W_h + b_h), 12.8 MB
__device__ __align__(16) float g_wx[(size_t)N_NODES * 4]; // (w, w*x0, w*x1, w*x2)
__device__ int g_cnt[N_NODES];
__device__ int g_bucket[(size_t)N_NODES * CAP];
__device__ int g_idx_is64;

// ---------------------------------------------------------------------------
// Kernel 0: zero counts + detect edge_index dtype (int32 masquerading as
// int64 when jax x64 mode is off: real int64 < 50000 has zero odd words).
// ---------------------------------------------------------------------------
__global__ __launch_bounds__(256) void init_kernel(const int* __restrict__ ei32)
{
    int i = blockIdx.x * blockDim.x + threadIdx.x;
    if (i < N_NODES) g_cnt[i] = 0;
    if (blockIdx.x == 0 && threadIdx.x < 32) {
        int odd = ei32[2 * threadIdx.x + 1];
        unsigned nz = __ballot_sync(0xffffffffu, odd != 0);
        if (threadIdx.x == 0) g_idx_is64 = (nz == 0u);
    }
}

// ---------------------------------------------------------------------------
// Kernel 1: per-node precompute (runs on SIDE stream, overlapped with
// init+scatter). One warp per node: M = relu(h @ W_h + b_h); w = relu(h.W_x
// + b_x); also stores the packed (w, w*x) 4-vector for the agg kernel.
// ---------------------------------------------------------------------------
__global__ __launch_bounds__(256) void node_kernel(
    const float* __restrict__ h, const float* __restrict__ x,
    const float* __restrict__ W_h, const float* __restrict__ b_h,
    const float* __restrict__ W_x, const float* __restrict__ b_x)
{
    __shared__ float Ws[D][D];
    __shared__ float Wxs[D];
    __shared__ float bhs[D];

    int tid = threadIdx.x;
    for (int i = tid; i < D * D; i += blockDim.x)
        Ws[i >> 6][i & 63] = W_h[i];
    if (tid < D) { Wxs[tid] = W_x[tid]; bhs[tid] = b_h[tid]; }
    __syncthreads();

    int warp = tid >> 5, lane = tid & 31;
    int node = blockIdx.x * (blockDim.x >> 5) + warp;
    if (node >= N_NODES) return;

    const float* hr = h + (size_t)node * D;
    float h0 = hr[lane];
    float h1 = hr[lane + 32];

    float m0 = 0.f, m1 = 0.f;
#pragma unroll
    for (int k = 0; k < 32; k++) {
        float hk = __shfl_sync(0xffffffffu, h0, k);
        m0 = fmaf(hk, Ws[k][lane], m0);
        m1 = fmaf(hk, Ws[k][lane + 32], m1);
    }
#pragma unroll
    for (int k = 0; k < 32; k++) {
        float hk = __shfl_sync(0xffffffffu, h1, k);
        m0 = fmaf(hk, Ws[k + 32][lane], m0);
        m1 = fmaf(hk, Ws[k + 32][lane + 32], m1);
    }
    g_M[(size_t)node * D + lane]      = fmaxf(m0 + bhs[lane], 0.f);
    g_M[(size_t)node * D + lane + 32] = fmaxf(m1 + bhs[lane + 32], 0.f);

    float wacc = fmaf(h0, Wxs[lane], h1 * Wxs[lane + 32]);
#pragma unroll
    for (int o = 16; o > 0; o >>= 1)
        wacc += __shfl_xor_sync(0xffffffffu, wacc, o);
    float w = fmaxf(wacc + b_x[0], 0.f);   // all lanes hold w

    if (lane < 4) {
        float v = (lane == 0) ? w : w * x[(size_t)node * 3 + (lane - 1)];
        g_wx[(size_t)node * 4 + lane] = v;
    }
}

// ---------------------------------------------------------------------------
// Kernel 2: bucket edges by destination (int atomics over 50000 addrs only).
// ---------------------------------------------------------------------------
__global__ __launch_bounds__(256) void scatter_kernel(const void* __restrict__ ei_raw)
{
    int e = blockIdx.x * blockDim.x + threadIdx.x;
    if (e >= N_EDGES) return;
    int row, col;
    if (g_idx_is64) {
        row = (int)((const long long*)ei_raw)[e];
        col = (int)((const long long*)ei_raw)[(size_t)N_EDGES + e];
    } else {
        row = ((const int*)ei_raw)[e];
        col = ((const int*)ei_raw)[(size_t)N_EDGES + e];
    }
    int pos = atomicAdd(&g_cnt[row], 1);
    if (pos < CAP) g_bucket[(size_t)row * CAP + pos] = col;
}

// ---------------------------------------------------------------------------
// Kernel 3: atomic-free aggregation. One warp per node. Per 8-edge batch:
// 8 independent LDG.64 of M rows (each lane one float2 of the 64-float row)
// + ONE scalar LDG.32 of g_wx (lane l -> edge l>>2, component l&3), covering
// the entire x-side math. agg_x = x*(Σw) − Σ(w·x_col), recovered by a
// stride-4 xor reduction at the end.
// ---------------------------------------------------------------------------
__global__ __launch_bounds__(256) void agg_kernel(
    const float* __restrict__ h, const float* __restrict__ x,
    float* __restrict__ h_out, float* __restrict__ x_out)
{
    const unsigned FULL = 0xffffffffu;
    int warp = threadIdx.x >> 5, lane = threadIdx.x & 31;
    int node = blockIdx.x * (blockDim.x >> 5) + warp;
    if (node >= N_NODES) return;

    int deg = g_cnt[node];
    if (deg > CAP) deg = CAP;
    const int* bk = g_bucket + (size_t)node * CAP;

    int comp = lane & 3;
    int kgrp = lane >> 2;
    float xr = (lane < 3) ? x[(size_t)node * 3 + lane] : 0.f;

    float2 a0 = make_float2(0.f, 0.f), a1 = make_float2(0.f, 0.f);
    float awx = 0.f;

    for (int base = 0; base < deg; base += 32) {
        int n = deg - base; if (n > 32) n = 32;
        int colv = (base + lane < deg) ? bk[base + lane] : 0;

        int j = 0;
        for (; j + 8 <= n; j += 8) {
            int c0 = __shfl_sync(FULL, colv, j);
            int c1 = __shfl_sync(FULL, colv, j + 1);
            int c2 = __shfl_sync(FULL, colv, j + 2);
            int c3 = __shfl_sync(FULL, colv, j + 3);
            int c4 = __shfl_sync(FULL, colv, j + 4);
            int c5 = __shfl_sync(FULL, colv, j + 5);
            int c6 = __shfl_sync(FULL, colv, j + 6);
            int c7 = __shfl_sync(FULL, colv, j + 7);
            int cs = __shfl_sync(FULL, colv, j + kgrp);

            float2 m0 = ((const float2*)(g_M + (size_t)c0 * D))[lane];
            float2 m1 = ((const float2*)(g_M + (size_t)c1 * D))[lane];
            float2 m2 = ((const float2*)(g_M + (size_t)c2 * D))[lane];
            float2 m3 = ((const float2*)(g_M + (size_t)c3 * D))[lane];
            float2 m4 = ((const float2*)(g_M + (size_t)c4 * D))[lane];
            float2 m5 = ((const float2*)(g_M + (size_t)c5 * D))[lane];
            float2 m6 = ((const float2*)(g_M + (size_t)c6 * D))[lane];
            float2 m7 = ((const float2*)(g_M + (size_t)c7 * D))[lane];
            float wv  = g_wx[(size_t)cs * 4 + comp];

            a0.x += (m0.x + m1.x) + (m2.x + m3.x);
            a0.y += (m0.y + m1.y) + (m2.y + m3.y);
            a1.x += (m4.x + m5.x) + (m6.x + m7.x);
            a1.y += (m4.y + m5.y) + (m6.y + m7.y);
            awx  += wv;
        }
        for (; j < n; j++) {
            int c = __shfl_sync(FULL, colv, j);
            float2 m = ((const float2*)(g_M + (size_t)c * D))[lane];
            a0.x += m.x; a0.y += m.y;
            if (kgrp == 0) awx += g_wx[(size_t)c * 4 + comp];  // group 0 only
        }
    }

    // reduce awx across the 8 k-groups (components stay in place)
    awx += __shfl_xor_sync(FULL, awx, 4);
    awx += __shfl_xor_sync(FULL, awx, 8);
    awx += __shfl_xor_sync(FULL, awx, 16);
    float sw  = __shfl_sync(FULL, awx, 0);          // Σ w
    float swx = __shfl_sync(FULL, awx, (lane & 3) == lane ? lane + 1 : 1);
    // lanes 0..2 need comp (lane+1); the shfl above gives lane l<3 -> lane l+1

    float2 hv = ((const float2*)(h + (size_t)node * D))[lane];
    float2 out = make_float2(hv.x + a0.x + a1.x, hv.y + a0.y + a1.y);
    ((float2*)(h_out + (size_t)node * D))[lane] = out;
    if (lane < 3) x_out[(size_t)node * 3 + lane] = xr + xr * sw - swx;
}

// ---------------------------------------------------------------------------
extern "C" void kernel_launch(void* const* d_in, const int* in_sizes, int n_in,
                              void* d_out, int out_size)
{
    const float* h   = (const float*)d_in[0];
    const float* x   = (const float*)d_in[1];
    const void*  ei  = d_in[2];
    const float* W_h = (const float*)d_in[3];
    const float* b_h = (const float*)d_in[4];
    const float* W_x = (const float*)d_in[5];
    const float* b_x = (const float*)d_in[6];

    float* h_out = (float*)d_out;
    float* x_out = (float*)d_out + (size_t)N_NODES * D;

    // Lazy side-stream/events (created on the first call, which is the
    // non-captured correctness run; never created during capture).
    static cudaStream_t s_side = nullptr;
    static cudaEvent_t ev_fork = nullptr, ev_join = nullptr;
    if (!s_side) {
        cudaStreamCreateWithFlags(&s_side, cudaStreamNonBlocking);
        cudaEventCreateWithFlags(&ev_fork, cudaEventDisableTiming);
        cudaEventCreateWithFlags(&ev_join, cudaEventDisableTiming);
    }

    int nodes_per_block = 256 / 32;
    int nblocks = (N_NODES + nodes_per_block - 1) / nodes_per_block;

    // Fork: node_kernel (independent of edge bucketing) on side stream.
    cudaEventRecord(ev_fork, 0);
    cudaStreamWaitEvent(s_side, ev_fork, 0);
    node_kernel<<<nblocks, 256, 0, s_side>>>(h, x, W_h, b_h, W_x, b_x);
    cudaEventRecord(ev_join, s_side);

    // Main stream: init -> scatter (overlapped with node_kernel).
    init_kernel<<<(N_NODES + 255) / 256, 256>>>((const int*)ei);
    scatter_kernel<<<(N_EDGES + 255) / 256, 256>>>(ei);

    // Join, then aggregate.
    cudaStreamWaitEvent(0, ev_join, 0);
    agg_kernel<<<nblocks, 256>>>(h, x, h_out, x_out);
}

// round 5
// speedup vs baseline: 1.5081x; 1.5081x over previous
#include <cuda_runtime.h>
#include <cuda_bf16.h>

#define N_NODES 50000
#define N_EDGES 800000
#define D 64
#define CAP 128   // bucket capacity; P(deg>=128 | Poisson(16)) < 1e-60
#define FULL 0xffffffffu

// Scratch (device globals — no allocation allowed in kernel_launch)
__device__ __align__(16) float g_M[(size_t)N_NODES * D];  // relu(h @ W_h + b_h), 12.8 MB
__device__ __align__(16) float g_wx[(size_t)N_NODES * 4]; // (w, w*x0, w*x1, w*x2)
__device__ int g_cnt[N_NODES];
__device__ int g_bucket[(size_t)N_NODES * CAP];
__device__ int g_idx_is64;

// ---------------------------------------------------------------------------
// Kernel 1 (persistent): detect dtype + zero counts + per-node precompute.
// W_h staged in shared ONCE per block; each warp loops over ~21 nodes.
// M = relu(h @ W_h + b_h); packed (w, w*x) with w = relu(h . W_x + b_x).
// ---------------------------------------------------------------------------
#define NODE_BLOCKS 296

__global__ __launch_bounds__(256) void node_kernel(
    const float* __restrict__ h, const float* __restrict__ x,
    const float* __restrict__ W_h, const float* __restrict__ b_h,
    const float* __restrict__ W_x, const float* __restrict__ b_x,
    const int* __restrict__ ei32)
{
    __shared__ float Ws[D][D];   // Ws[k][d]
    __shared__ float Wxs[D];
    __shared__ float bhs[D];

    int tid = threadIdx.x;

    // dtype detect: jax.random.randint(dtype=int64) silently yields int32
    // without x64 mode; true int64 values < 50000 have zero odd words.
    if (blockIdx.x == 0 && tid < 32) {
        int odd = ei32[2 * tid + 1];
        unsigned nz = __ballot_sync(FULL, odd != 0);
        if (tid == 0) g_idx_is64 = (nz == 0u);
    }
    // zero bucket counters (used by scatter_kernel, next in stream order)
    for (int i = blockIdx.x * 256 + tid; i < N_NODES; i += NODE_BLOCKS * 256)
        g_cnt[i] = 0;

    // stage weights once per block
    for (int i = tid; i < D * D; i += 256)
        Ws[i >> 6][i & 63] = W_h[i];
    if (tid < D) { Wxs[tid] = W_x[tid]; bhs[tid] = b_h[tid]; }
    __syncthreads();

    int warp = tid >> 5, lane = tid & 31;
    int gw = blockIdx.x * 8 + warp;
    float bh0 = bhs[lane], bh1 = bhs[lane + 32];
    float wx0 = Wxs[lane], wx1 = Wxs[lane + 32];

    for (int node = gw; node < N_NODES; node += NODE_BLOCKS * 8) {
        const float* hr = h + (size_t)node * D;
        float h0 = hr[lane];
        float h1 = hr[lane + 32];

        float m0 = 0.f, m1 = 0.f;
#pragma unroll
        for (int k = 0; k < 32; k++) {
            float hk = __shfl_sync(FULL, h0, k);
            m0 = fmaf(hk, Ws[k][lane], m0);
            m1 = fmaf(hk, Ws[k][lane + 32], m1);
        }
#pragma unroll
        for (int k = 0; k < 32; k++) {
            float hk = __shfl_sync(FULL, h1, k);
            m0 = fmaf(hk, Ws[k + 32][lane], m0);
            m1 = fmaf(hk, Ws[k + 32][lane + 32], m1);
        }
        g_M[(size_t)node * D + lane]      = fmaxf(m0 + bh0, 0.f);
        g_M[(size_t)node * D + lane + 32] = fmaxf(m1 + bh1, 0.f);

        float wacc = fmaf(h0, wx0, h1 * wx1);
#pragma unroll
        for (int o = 16; o > 0; o >>= 1)
            wacc += __shfl_xor_sync(FULL, wacc, o);
        float w = fmaxf(wacc + b_x[0], 0.f);   // all lanes hold w

        if (lane < 4) {
            float v = (lane == 0) ? w : w * x[(size_t)node * 3 + (lane - 1)];
            g_wx[(size_t)node * 4 + lane] = v;
        }
    }
}

// ---------------------------------------------------------------------------
// Kernel 2: bucket edges by destination (int atomics over 50000 addrs only).
// ---------------------------------------------------------------------------
__global__ __launch_bounds__(256) void scatter_kernel(const void* __restrict__ ei_raw)
{
    int e = blockIdx.x * blockDim.x + threadIdx.x;
    if (e >= N_EDGES) return;
    int row, col;
    if (g_idx_is64) {
        row = (int)((const long long*)ei_raw)[e];
        col = (int)((const long long*)ei_raw)[(size_t)N_EDGES + e];
    } else {
        row = ((const int*)ei_raw)[e];
        col = ((const int*)ei_raw)[(size_t)N_EDGES + e];
    }
    int pos = atomicAdd(&g_cnt[row], 1);
    if (pos < CAP) g_bucket[(size_t)row * CAP + pos] = col;
}

// ---------------------------------------------------------------------------
// Kernel 3: atomic-free aggregation. One warp per node. Per 32-edge chunk:
//   prologue: 4 LDG.32 of packed g_wx (lane -> edge 8r + (lane>>2),
//             component lane&3) cover the ENTIRE x-side math for the chunk;
//   main:     4-deep batches of coalesced LDG.64 M-row gathers (32 regs,
//             the R3 occupancy sweet spot).
// agg_x = x*(Σw) − Σ(w·x_col), recovered by a stride-4 xor reduction.
// ---------------------------------------------------------------------------
__global__ __launch_bounds__(256) void agg_kernel(
    const float* __restrict__ h, const float* __restrict__ x,
    float* __restrict__ h_out, float* __restrict__ x_out)
{
    int warp = threadIdx.x >> 5, lane = threadIdx.x & 31;
    int node = blockIdx.x * (blockDim.x >> 5) + warp;
    if (node >= N_NODES) return;

    int deg = g_cnt[node];
    if (deg > CAP) deg = CAP;
    const int* bk = g_bucket + (size_t)node * CAP;

    int comp = lane & 3;
    int kgrp = lane >> 2;          // 0..7
    float xr = (lane < 3) ? x[(size_t)node * 3 + lane] : 0.f;

    float2 acc = make_float2(0.f, 0.f);
    float awx = 0.f;

    for (int base = 0; base < deg; base += 32) {
        int n = deg - base; if (n > 32) n = 32;
        int colv = (base + lane < deg) ? bk[base + lane] : 0;

        // x-side: 4 packed loads cover all n edges of this chunk
#pragma unroll
        for (int r = 0; r < 4; r++) {
            int j2 = r * 8 + kgrp;
            int cs = __shfl_sync(FULL, colv, j2);
            if (j2 < n) awx += g_wx[(size_t)cs * 4 + comp];
        }

        // h-side: 4-deep float2 gathers
        int j = 0;
        for (; j + 4 <= n; j += 4) {
            int c0 = __shfl_sync(FULL, colv, j);
            int c1 = __shfl_sync(FULL, colv, j + 1);
            int c2 = __shfl_sync(FULL, colv, j + 2);
            int c3 = __shfl_sync(FULL, colv, j + 3);
            float2 m0 = ((const float2*)(g_M + (size_t)c0 * D))[lane];
            float2 m1 = ((const float2*)(g_M + (size_t)c1 * D))[lane];
            float2 m2 = ((const float2*)(g_M + (size_t)c2 * D))[lane];
            float2 m3 = ((const float2*)(g_M + (size_t)c3 * D))[lane];
            acc.x += (m0.x + m1.x) + (m2.x + m3.x);
            acc.y += (m0.y + m1.y) + (m2.y + m3.y);
        }
        for (; j < n; j++) {
            int c = __shfl_sync(FULL, colv, j);
            float2 m = ((const float2*)(g_M + (size_t)c * D))[lane];
            acc.x += m.x; acc.y += m.y;
        }
    }

    // reduce awx across the 8 k-groups; components stay in lanes 0..3
    awx += __shfl_xor_sync(FULL, awx, 4);
    awx += __shfl_xor_sync(FULL, awx, 8);
    awx += __shfl_xor_sync(FULL, awx, 16);
    float sw  = __shfl_sync(FULL, awx, 0);                       // Σ w
    float swx = __shfl_sync(FULL, awx, (lane < 3) ? lane + 1 : 0); // Σ w*x_col[lane]

    float2 hv = ((const float2*)(h + (size_t)node * D))[lane];
    ((float2*)(h_out + (size_t)node * D))[lane] =
        make_float2(hv.x + acc.x, hv.y + acc.y);
    if (lane < 3) x_out[(size_t)node * 3 + lane] = xr + xr * sw - swx;
}

// ---------------------------------------------------------------------------
extern "C" void kernel_launch(void* const* d_in, const int* in_sizes, int n_in,
                              void* d_out, int out_size)
{
    const float* h   = (const float*)d_in[0];
    const float* x   = (const float*)d_in[1];
    const void*  ei  = d_in[2];
    const float* W_h = (const float*)d_in[3];
    const float* b_h = (const float*)d_in[4];
    const float* W_x = (const float*)d_in[5];
    const float* b_x = (const float*)d_in[6];

    float* h_out = (float*)d_out;
    float* x_out = (float*)d_out + (size_t)N_NODES * D;

    node_kernel<<<NODE_BLOCKS, 256>>>(h, x, W_h, b_h, W_x, b_x, (const int*)ei);

    scatter_kernel<<<(N_EDGES + 255) / 256, 256>>>(ei);

    int nblocks = (N_NODES + 7) / 8;   // 8 warps/block, 1 node/warp
    agg_kernel<<<nblocks, 256>>>(h, x, h_out, x_out);
}

// round 6
// speedup vs baseline: 1.6702x; 1.1075x over previous
#include <cuda_runtime.h>
#include <cuda_bf16.h>

#define N_NODES 50000
#define N_EDGES 800000
#define D 64
#define CAP 128   // bucket capacity; P(deg>=128 | Poisson(16)) < 1e-60
#define FULL 0xffffffffu

// Scratch (device globals — no allocation allowed in kernel_launch)
__device__ __align__(16) float g_M[(size_t)N_NODES * D];  // relu(h @ W_h + b_h), 12.8 MB
__device__ __align__(16) float g_wx[(size_t)N_NODES * 4]; // (w, w*x0, w*x1, w*x2)
__device__ int g_cnt[N_NODES];
__device__ int g_bucket[(size_t)N_NODES * CAP];
__device__ int g_idx_is64;

// ---------------------------------------------------------------------------
// Kernel 1 (persistent, FULL occupancy): detect dtype + zero counts +
// per-node precompute. 1184 blocks = 8 blocks/SM @ 256 thr/32 reg -> occ 100%.
// Lane l owns dims (2l, 2l+1): weight read is one LDS.64 per k, M store is
// one STG.64. h row broadcast via shfl as before.
// ---------------------------------------------------------------------------
#define NODE_BLOCKS 1184

__global__ __launch_bounds__(256) void node_kernel(
    const float* __restrict__ h, const float* __restrict__ x,
    const float* __restrict__ W_h, const float* __restrict__ b_h,
    const float* __restrict__ W_x, const float* __restrict__ b_x,
    const int* __restrict__ ei32)
{
    __shared__ float Ws[D * D];    // row-major W_h[k][d]
    __shared__ float Wxs[D];
    __shared__ float bhs[D];

    int tid = threadIdx.x;

    // dtype detect: jax.random.randint(dtype=int64) silently yields int32
    // without x64 mode; true int64 values < 50000 have zero odd words.
    if (blockIdx.x == 0 && tid < 32) {
        int odd = ei32[2 * tid + 1];
        unsigned nz = __ballot_sync(FULL, odd != 0);
        if (tid == 0) g_idx_is64 = (nz == 0u);
    }
    // zero bucket counters (consumed by scatter_kernel, later in stream)
    for (int i = blockIdx.x * 256 + tid; i < N_NODES; i += NODE_BLOCKS * 256)
        g_cnt[i] = 0;

    for (int i = tid; i < D * D; i += 256) Ws[i] = W_h[i];
    if (tid < D) { Wxs[tid] = W_x[tid]; bhs[tid] = b_h[tid]; }
    __syncthreads();

    int warp = tid >> 5, lane = tid & 31;
    const float2* Wsv = (const float2*)Ws;          // Wsv[k*32 + l] = W[k][2l..2l+1]
    float2 bh2 = ((const float2*)bhs)[lane];
    float wx0 = Wxs[lane], wx1 = Wxs[lane + 32];

    for (int node = blockIdx.x * 8 + warp; node < N_NODES; node += NODE_BLOCKS * 8) {
        const float* hr = h + (size_t)node * D;
        float h0 = hr[lane];
        float h1 = hr[lane + 32];

        float2 acc = make_float2(0.f, 0.f);
#pragma unroll
        for (int k = 0; k < 32; k++) {
            float hk = __shfl_sync(FULL, h0, k);
            float2 w2 = Wsv[k * 32 + lane];
            acc.x = fmaf(hk, w2.x, acc.x);
            acc.y = fmaf(hk, w2.y, acc.y);
        }
#pragma unroll
        for (int k = 0; k < 32; k++) {
            float hk = __shfl_sync(FULL, h1, k);
            float2 w2 = Wsv[(k + 32) * 32 + lane];
            acc.x = fmaf(hk, w2.x, acc.x);
            acc.y = fmaf(hk, w2.y, acc.y);
        }
        ((float2*)(g_M + (size_t)node * D))[lane] =
            make_float2(fmaxf(acc.x + bh2.x, 0.f), fmaxf(acc.y + bh2.y, 0.f));

        float wacc = fmaf(h0, wx0, h1 * wx1);
#pragma unroll
        for (int o = 16; o > 0; o >>= 1)
            wacc += __shfl_xor_sync(FULL, wacc, o);
        float w = fmaxf(wacc + b_x[0], 0.f);       // all lanes hold w

        if (lane < 4) {
            float v = (lane == 0) ? w : w * x[(size_t)node * 3 + (lane - 1)];
            g_wx[(size_t)node * 4 + lane] = v;
        }
    }
}

// ---------------------------------------------------------------------------
// Kernel 2: bucket edges by destination (int atomics over 50000 addrs only).
// ---------------------------------------------------------------------------
__global__ __launch_bounds__(256) void scatter_kernel(const void* __restrict__ ei_raw)
{
    int e = blockIdx.x * blockDim.x + threadIdx.x;
    if (e >= N_EDGES) return;
    int row, col;
    if (g_idx_is64) {
        row = (int)((const long long*)ei_raw)[e];
        col = (int)((const long long*)ei_raw)[(size_t)N_EDGES + e];
    } else {
        row = ((const int*)ei_raw)[e];
        col = ((const int*)ei_raw)[(size_t)N_EDGES + e];
    }
    int pos = atomicAdd(&g_cnt[row], 1);
    if (pos < CAP) g_bucket[(size_t)row * CAP + pos] = col;
}

// ---------------------------------------------------------------------------
// Kernel 3: atomic-free aggregation (R3/R5 sweet spot: 32 regs, 78% occ).
// One warp per node. Per 32-edge chunk: 4 packed g_wx loads cover the entire
// x-side; 4-deep batches of coalesced LDG.64 M-row gathers for the h-side.
// agg_x = x*(Σw) − Σ(w·x_col), recovered via stride-4 xor reduction.
// ---------------------------------------------------------------------------
__global__ __launch_bounds__(256) void agg_kernel(
    const float* __restrict__ h, const float* __restrict__ x,
    float* __restrict__ h_out, float* __restrict__ x_out)
{
    int warp = threadIdx.x >> 5, lane = threadIdx.x & 31;
    int node = blockIdx.x * (blockDim.x >> 5) + warp;
    if (node >= N_NODES) return;

    int deg = g_cnt[node];
    if (deg > CAP) deg = CAP;
    const int* bk = g_bucket + (size_t)node * CAP;

    int comp = lane & 3;
    int kgrp = lane >> 2;          // 0..7
    float xr = (lane < 3) ? x[(size_t)node * 3 + lane] : 0.f;

    float2 acc = make_float2(0.f, 0.f);
    float awx = 0.f;

    for (int base = 0; base < deg; base += 32) {
        int n = deg - base; if (n > 32) n = 32;
        int colv = (base + lane < deg) ? bk[base + lane] : 0;

#pragma unroll
        for (int r = 0; r < 4; r++) {
            int j2 = r * 8 + kgrp;
            int cs = __shfl_sync(FULL, colv, j2);
            if (j2 < n) awx += g_wx[(size_t)cs * 4 + comp];
        }

        int j = 0;
        for (; j + 4 <= n; j += 4) {
            int c0 = __shfl_sync(FULL, colv, j);
            int c1 = __shfl_sync(FULL, colv, j + 1);
            int c2 = __shfl_sync(FULL, colv, j + 2);
            int c3 = __shfl_sync(FULL, colv, j + 3);
            float2 m0 = ((const float2*)(g_M + (size_t)c0 * D))[lane];
            float2 m1 = ((const float2*)(g_M + (size_t)c1 * D))[lane];
            float2 m2 = ((const float2*)(g_M + (size_t)c2 * D))[lane];
            float2 m3 = ((const float2*)(g_M + (size_t)c3 * D))[lane];
            acc.x += (m0.x + m1.x) + (m2.x + m3.x);
            acc.y += (m0.y + m1.y) + (m2.y + m3.y);
        }
        for (; j < n; j++) {
            int c = __shfl_sync(FULL, colv, j);
            float2 m = ((const float2*)(g_M + (size_t)c * D))[lane];
            acc.x += m.x; acc.y += m.y;
        }
    }

    awx += __shfl_xor_sync(FULL, awx, 4);
    awx += __shfl_xor_sync(FULL, awx, 8);
    awx += __shfl_xor_sync(FULL, awx, 16);
    float sw  = __shfl_sync(FULL, awx, 0);                         // Σ w
    float swx = __shfl_sync(FULL, awx, (lane < 3) ? lane + 1 : 0); // Σ w*x_col[lane]

    float2 hv = ((const float2*)(h + (size_t)node * D))[lane];
    ((float2*)(h_out + (size_t)node * D))[lane] =
        make_float2(hv.x + acc.x, hv.y + acc.y);
    if (lane < 3) x_out[(size_t)node * 3 + lane] = xr + xr * sw - swx;
}

// ---------------------------------------------------------------------------
extern "C" void kernel_launch(void* const* d_in, const int* in_sizes, int n_in,
                              void* d_out, int out_size)
{
    const float* h   = (const float*)d_in[0];
    const float* x   = (const float*)d_in[1];
    const void*  ei  = d_in[2];
    const float* W_h = (const float*)d_in[3];
    const float* b_h = (const float*)d_in[4];
    const float* W_x = (const float*)d_in[5];
    const float* b_x = (const float*)d_in[6];

    float* h_out = (float*)d_out;
    float* x_out = (float*)d_out + (size_t)N_NODES * D;

    node_kernel<<<NODE_BLOCKS, 256>>>(h, x, W_h, b_h, W_x, b_x, (const int*)ei);

    scatter_kernel<<<(N_EDGES + 255) / 256, 256>>>(ei);

    int nblocks = (N_NODES + 7) / 8;   // 8 warps/block, 1 node/warp
    agg_kernel<<<nblocks, 256>>>(h, x, h_out, x_out);
}

// round 7
// speedup vs baseline: 2.0548x; 1.2303x over previous
#include <cuda_runtime.h>
#include <cuda_bf16.h>

#define N_NODES 50000
#define N_EDGES 800000
#define D 64
#define CAP 128   // bucket capacity; P(deg>=128 | Poisson(16)) < 1e-60
#define FULL 0xffffffffu

// Scratch (device globals — no allocation allowed in kernel_launch)
__device__ __align__(16) float g_M[(size_t)N_NODES * D];  // relu(h @ W_h + b_h), 12.8 MB
__device__ __align__(16) float g_wx[(size_t)N_NODES * 4]; // (w, w*x0, w*x1, w*x2)
__device__ int g_cnt[N_NODES];
__device__ int g_bucket[(size_t)N_NODES * CAP];
__device__ int g_idx_is64;

// ---------------------------------------------------------------------------
// Kernel 1: detect dtype + zero counts + per-node precompute.
// 4 nodes per warp: each LDS.64 weight read is shared by 4 nodes (4 shfl +
// 8 FMA per read), cutting smem-crossbar traffic 4x vs 1 node/warp.
// Lane l owns output dims (2l, 2l+1).
// ---------------------------------------------------------------------------
__global__ __launch_bounds__(256) void node_kernel(
    const float* __restrict__ h, const float* __restrict__ x,
    const float* __restrict__ W_h, const float* __restrict__ b_h,
    const float* __restrict__ W_x, const float* __restrict__ b_x,
    const int* __restrict__ ei32)
{
    __shared__ float Ws[D * D];    // row-major W_h[k][d]
    __shared__ float Wxs[D];
    __shared__ float bhs[D];

    int tid = threadIdx.x;
    int nblk = gridDim.x;

    // dtype detect: jax.random.randint(dtype=int64) silently yields int32
    // without x64 mode; true int64 values < 50000 have zero odd words.
    if (blockIdx.x == 0 && tid < 32) {
        int odd = ei32[2 * tid + 1];
        unsigned nz = __ballot_sync(FULL, odd != 0);
        if (tid == 0) g_idx_is64 = (nz == 0u);
    }
    // zero bucket counters (consumed by scatter_kernel, later in stream)
    for (int i = blockIdx.x * 256 + tid; i < N_NODES; i += nblk * 256)
        g_cnt[i] = 0;

    for (int i = tid; i < D * D; i += 256) Ws[i] = W_h[i];
    if (tid < D) { Wxs[tid] = W_x[tid]; bhs[tid] = b_h[tid]; }
    __syncthreads();

    int warp = tid >> 5, lane = tid & 31;
    const float2* Wsv = (const float2*)Ws;          // Wsv[k*32 + l] = W[k][2l..2l+1]
    float2 bh2 = ((const float2*)bhs)[lane];
    float wxa = Wxs[lane], wxb = Wxs[lane + 32];
    float bx0 = b_x[0];

    // 4 consecutive nodes per warp; 32 nodes per block.
    int nb = (blockIdx.x * 8 + warp) * 4;
    if (nb >= N_NODES) return;

    float h0[4], h1[4];
    float2 acc[4];
#pragma unroll
    for (int i = 0; i < 4; i++) {
        int node = nb + i;
        const float* hr = h + (size_t)min(node, N_NODES - 1) * D;
        h0[i] = hr[lane];
        h1[i] = hr[lane + 32];
        acc[i] = make_float2(0.f, 0.f);
    }

#pragma unroll
    for (int k = 0; k < 32; k++) {
        float2 w2 = Wsv[k * 32 + lane];
#pragma unroll
        for (int i = 0; i < 4; i++) {
            float hk = __shfl_sync(FULL, h0[i], k);
            acc[i].x = fmaf(hk, w2.x, acc[i].x);
            acc[i].y = fmaf(hk, w2.y, acc[i].y);
        }
    }
#pragma unroll
    for (int k = 0; k < 32; k++) {
        float2 w2 = Wsv[(k + 32) * 32 + lane];
#pragma unroll
        for (int i = 0; i < 4; i++) {
            float hk = __shfl_sync(FULL, h1[i], k);
            acc[i].x = fmaf(hk, w2.x, acc[i].x);
            acc[i].y = fmaf(hk, w2.y, acc[i].y);
        }
    }

#pragma unroll
    for (int i = 0; i < 4; i++) {
        int node = nb + i;
        if (node >= N_NODES) break;
        ((float2*)(g_M + (size_t)node * D))[lane] =
            make_float2(fmaxf(acc[i].x + bh2.x, 0.f), fmaxf(acc[i].y + bh2.y, 0.f));

        float wacc = fmaf(h0[i], wxa, h1[i] * wxb);
#pragma unroll
        for (int o = 16; o > 0; o >>= 1)
            wacc += __shfl_xor_sync(FULL, wacc, o);
        float w = fmaxf(wacc + bx0, 0.f);          // all lanes hold w

        if (lane < 4) {
            float v = (lane == 0) ? w : w * x[(size_t)node * 3 + (lane - 1)];
            g_wx[(size_t)node * 4 + lane] = v;
        }
    }
}

// ---------------------------------------------------------------------------
// Kernel 2: bucket edges by destination (int atomics over 50000 addrs only).
// ---------------------------------------------------------------------------
__global__ __launch_bounds__(256) void scatter_kernel(const void* __restrict__ ei_raw)
{
    int e = blockIdx.x * blockDim.x + threadIdx.x;
    if (e >= N_EDGES) return;
    int row, col;
    if (g_idx_is64) {
        row = (int)((const long long*)ei_raw)[e];
        col = (int)((const long long*)ei_raw)[(size_t)N_EDGES + e];
    } else {
        row = ((const int*)ei_raw)[e];
        col = ((const int*)ei_raw)[(size_t)N_EDGES + e];
    }
    int pos = atomicAdd(&g_cnt[row], 1);
    if (pos < CAP) g_bucket[(size_t)row * CAP + pos] = col;
}

// ---------------------------------------------------------------------------
// Kernel 3: atomic-free aggregation (32 regs / 78% occ sweet spot).
// One warp per node. Per 32-edge chunk: 4 packed g_wx loads cover the entire
// x-side; 4-deep batches of coalesced LDG.64 M-row gathers for the h-side.
// agg_x = x*(Σw) − Σ(w·x_col), recovered via stride-4 xor reduction.
// ---------------------------------------------------------------------------
__global__ __launch_bounds__(256) void agg_kernel(
    const float* __restrict__ h, const float* __restrict__ x,
    float* __restrict__ h_out, float* __restrict__ x_out)
{
    int warp = threadIdx.x >> 5, lane = threadIdx.x & 31;
    int node = blockIdx.x * (blockDim.x >> 5) + warp;
    if (node >= N_NODES) return;

    int deg = g_cnt[node];
    if (deg > CAP) deg = CAP;
    const int* bk = g_bucket + (size_t)node * CAP;

    int comp = lane & 3;
    int kgrp = lane >> 2;          // 0..7
    float xr = (lane < 3) ? x[(size_t)node * 3 + lane] : 0.f;

    float2 acc = make_float2(0.f, 0.f);
    float awx = 0.f;

    for (int base = 0; base < deg; base += 32) {
        int n = deg - base; if (n > 32) n = 32;
        int colv = (base + lane < deg) ? bk[base + lane] : 0;

#pragma unroll
        for (int r = 0; r < 4; r++) {
            int j2 = r * 8 + kgrp;
            int cs = __shfl_sync(FULL, colv, j2);
            if (j2 < n) awx += g_wx[(size_t)cs * 4 + comp];
        }

        int j = 0;
        for (; j + 4 <= n; j += 4) {
            int c0 = __shfl_sync(FULL, colv, j);
            int c1 = __shfl_sync(FULL, colv, j + 1);
            int c2 = __shfl_sync(FULL, colv, j + 2);
            int c3 = __shfl_sync(FULL, colv, j + 3);
            float2 m0 = ((const float2*)(g_M + (size_t)c0 * D))[lane];
            float2 m1 = ((const float2*)(g_M + (size_t)c1 * D))[lane];
            float2 m2 = ((const float2*)(g_M + (size_t)c2 * D))[lane];
            float2 m3 = ((const float2*)(g_M + (size_t)c3 * D))[lane];
            acc.x += (m0.x + m1.x) + (m2.x + m3.x);
            acc.y += (m0.y + m1.y) + (m2.y + m3.y);
        }
        for (; j < n; j++) {
            int c = __shfl_sync(FULL, colv, j);
            float2 m = ((const float2*)(g_M + (size_t)c * D))[lane];
            acc.x += m.x; acc.y += m.y;
        }
    }

    awx += __shfl_xor_sync(FULL, awx, 4);
    awx += __shfl_xor_sync(FULL, awx, 8);
    awx += __shfl_xor_sync(FULL, awx, 16);
    float sw  = __shfl_sync(FULL, awx, 0);                         // Σ w
    float swx = __shfl_sync(FULL, awx, (lane < 3) ? lane + 1 : 0); // Σ w*x_col[lane]

    float2 hv = ((const float2*)(h + (size_t)node * D))[lane];
    ((float2*)(h_out + (size_t)node * D))[lane] =
        make_float2(hv.x + acc.x, hv.y + acc.y);
    if (lane < 3) x_out[(size_t)node * 3 + lane] = xr + xr * sw - swx;
}

// ---------------------------------------------------------------------------
extern "C" void kernel_launch(void* const* d_in, const int* in_sizes, int n_in,
                              void* d_out, int out_size)
{
    const float* h   = (const float*)d_in[0];
    const float* x   = (const float*)d_in[1];
    const void*  ei  = d_in[2];
    const float* W_h = (const float*)d_in[3];
    const float* b_h = (const float*)d_in[4];
    const float* W_x = (const float*)d_in[5];
    const float* b_x = (const float*)d_in[6];

    float* h_out = (float*)d_out;
    float* x_out = (float*)d_out + (size_t)N_NODES * D;

    // 32 nodes per block (8 warps x 4 nodes)
    int node_blocks = (N_NODES + 31) / 32;
    node_kernel<<<node_blocks, 256>>>(h, x, W_h, b_h, W_x, b_x, (const int*)ei);

    scatter_kernel<<<(N_EDGES + 255) / 256, 256>>>(ei);

    int nblocks = (N_NODES + 7) / 8;   // 8 warps/block, 1 node/warp
    agg_kernel<<<nblocks, 256>>>(h, x, h_out, x_out);
}